// round 16
// baseline (speedup 1.0000x reference)
#include <cuda_runtime.h>

#define NQ      12
#define NT      256         // threads per CTA
#define NR      16          // amplitudes per thread PER SAMPLE (2 samples interleaved)
#define NLAYERS 4
#define XP      17          // padded row pitch (in ulonglong2 elements)
#define XSZ     (NT * XP)   // ulonglong2 elements per exchange buffer
#define PHYS(n) ((n) + ((n) >> 4))   // (n>>4)*XP + (n&15)

typedef unsigned long long u64;

// ---- packed f32x2 helpers (re in lo 32 bits, im in hi 32 bits) ----
__device__ __forceinline__ u64 pack2(float lo, float hi) {
    u64 r; asm("mov.b64 %0, {%1, %2};" : "=l"(r) : "f"(lo), "f"(hi)); return r;
}
__device__ __forceinline__ void unpack2(u64 v, float& lo, float& hi) {
    asm("mov.b64 {%0, %1}, %2;" : "=f"(lo), "=f"(hi) : "l"(v));
}
__device__ __forceinline__ u64 swap2(u64 v) {
    u64 r;
    asm("{\n\t.reg .b32 l, h;\n\tmov.b64 {l, h}, %1;\n\tmov.b64 %0, {h, l};\n\t}"
        : "=l"(r) : "l"(v));
    return r;
}
__device__ __forceinline__ u64 ffma2(u64 a, u64 b, u64 c) {
    u64 r; asm("fma.rn.f32x2 %0, %1, %2, %3;" : "=l"(r) : "l"(a), "l"(b), "l"(c)); return r;
}
__device__ __forceinline__ u64 fmul2(u64 a, u64 b) {
    u64 r; asm("mul.rn.f32x2 %0, %1, %2;" : "=l"(r) : "l"(a), "l"(b)); return r;
}
__device__ __forceinline__ u64 add2(u64 a, u64 b) {
    u64 r; asm("add.rn.f32x2 %0, %1, %2;" : "=l"(r) : "l"(a), "l"(b)); return r;
}
__device__ __forceinline__ u64 neg2(u64 v) { return v ^ 0x8000000080000000ULL; }
__device__ __forceinline__ float2 cmul(float2 a, float2 b) {
    return make_float2(fmaf(-a.y, b.y, a.x * b.x), fmaf(a.y, b.x, a.x * b.y));
}

// State element: .x = sample-a amp (re,im packed), .y = sample-b amp.

// ---- REAL RY gate on register bit P, both samples (shared coeffs) ----
template<int P>
__device__ __forceinline__ void gate_ry2(ulonglong2* st, const u64* g) {
    ulonglong2 cs = *(const ulonglong2*)(g);   // C, S
    u64 NS = g[2];
#pragma unroll
    for (int k = 0; k < NR / 2; k++) {
        const int r0 = ((k >> P) << (P + 1)) | (k & ((1 << P) - 1));
        const int r1 = r0 | (1 << P);
        ulonglong2 m0 = st[r0], m1 = st[r1];
        st[r0].x = ffma2(NS,   m1.x, fmul2(cs.x, m0.x));
        st[r0].y = ffma2(NS,   m1.y, fmul2(cs.x, m0.y));
        st[r1].x = ffma2(cs.x, m1.x, fmul2(cs.y, m0.x));
        st[r1].y = ffma2(cs.x, m1.y, fmul2(cs.y, m0.y));
    }
}

// ======================= layouts & transposes (R13 schedule) =======================
// amp index n[11:0], wire q <-> bit (11-q). phys(n) = n + (n>>4) (ulonglong2 elems).
// Layout A: n = (t<<4)|r ; Layout C: n = ((t>>4)<<8)|(r<<4)|(t&15) ; Layout D: n = (r<<8)|t
// CTA round-trips alternate x0 (sweep) and x1 (cnot): one __syncthreads each.
// 16B elements: conflict-free iff element indices distinct mod 8 per quarter-warp —
// verified for A (17t ≡ t mod 8), C and D (8 consecutive indices).

#define ADDR_A(t, r) ((t) * XP + (r))
#define ADDR_C(t, r) (((((t) >> 4) << 4) | (r)) * XP + ((t) & 15))
#define ADDR_D(t, r) ((((r) << 4) | ((t) >> 4)) * XP + ((t) & 15))

__device__ __forceinline__ void exch_A_to_C(ulonglong2* st, int t, ulonglong2* x) { // WL
#pragma unroll
    for (int r = 0; r < NR; r++) x[ADDR_A(t, r)] = st[r];
    __syncwarp();
#pragma unroll
    for (int r = 0; r < NR; r++) st[r] = x[ADDR_C(t, r)];
    __syncwarp();
}
__device__ __forceinline__ void exch_C_to_A(ulonglong2* st, int t, ulonglong2* x) { // WL
#pragma unroll
    for (int r = 0; r < NR; r++) x[ADDR_C(t, r)] = st[r];
    __syncwarp();
#pragma unroll
    for (int r = 0; r < NR; r++) st[r] = x[ADDR_A(t, r)];
    __syncwarp();
}
__device__ __forceinline__ void exch_C_to_D(ulonglong2* st, int t, ulonglong2* x) { // CTA
#pragma unroll
    for (int r = 0; r < NR; r++) x[ADDR_C(t, r)] = st[r];
    __syncthreads();
#pragma unroll
    for (int r = 0; r < NR; r++) st[r] = x[ADDR_D(t, r)];
}
__device__ __forceinline__ void exch_D_to_C(ulonglong2* st, int t, ulonglong2* x) { // CTA
#pragma unroll
    for (int r = 0; r < NR; r++) x[ADDR_D(t, r)] = st[r];
    __syncthreads();
#pragma unroll
    for (int r = 0; r < NR; r++) st[r] = x[ADDR_C(t, r)];
    __syncwarp();   // reads are own-slice; order before this warp's next WL write
}

// ======================= RY-only sweeps =======================
__device__ __forceinline__ void sweep_A_to_D(ulonglong2* st, const u64* G, int t, ulonglong2* x) {
    gate_ry2<3>(st, G +  8 * 4);  gate_ry2<2>(st, G +  9 * 4);
    gate_ry2<1>(st, G + 10 * 4);  gate_ry2<0>(st, G + 11 * 4);
    exch_A_to_C(st, t, x);
    gate_ry2<3>(st, G +  4 * 4);  gate_ry2<2>(st, G +  5 * 4);
    gate_ry2<1>(st, G +  6 * 4);  gate_ry2<0>(st, G +  7 * 4);
    exch_C_to_D(st, t, x);
    gate_ry2<3>(st, G +  0 * 4);  gate_ry2<2>(st, G +  1 * 4);
    gate_ry2<1>(st, G +  2 * 4);  gate_ry2<0>(st, G +  3 * 4);
}
__device__ __forceinline__ void sweep_D_to_A(ulonglong2* st, const u64* G, int t, ulonglong2* x) {
    gate_ry2<3>(st, G +  0 * 4);  gate_ry2<2>(st, G +  1 * 4);
    gate_ry2<1>(st, G +  2 * 4);  gate_ry2<0>(st, G +  3 * 4);
    exch_D_to_C(st, t, x);
    gate_ry2<3>(st, G +  4 * 4);  gate_ry2<2>(st, G +  5 * 4);
    gate_ry2<1>(st, G +  6 * 4);  gate_ry2<0>(st, G +  7 * 4);
    exch_C_to_A(st, t, x);
    gate_ry2<3>(st, G +  8 * 4);  gate_ry2<2>(st, G +  9 * 4);
    gate_ry2<1>(st, G + 10 * 4);  gate_ry2<0>(st, G + 11 * 4);
}

// ======================= global diagonals (tables built once, applied to both) =======================
__device__ __forceinline__ void diag_A(ulonglong2* st, int t, const float2 (*P)[2]) {
    float2 p01 = cmul(P[0][(t >> 7) & 1], P[1][(t >> 6) & 1]);
    float2 p23 = cmul(P[2][(t >> 5) & 1], P[3][(t >> 4) & 1]);
    float2 p45 = cmul(P[4][(t >> 3) & 1], P[5][(t >> 2) & 1]);
    float2 p67 = cmul(P[6][(t >> 1) & 1], P[7][t & 1]);
    float2 ph  = cmul(cmul(p01, p23), cmul(p45, p67));
    u64 Ah[4], Bh[4], Al[4], Bl[4];
#pragma unroll
    for (int i = 0; i < 4; i++) {
        float2 hi = cmul(ph, cmul(P[8][(i >> 1) & 1], P[9][i & 1]));
        float2 lo = cmul(P[10][(i >> 1) & 1], P[11][i & 1]);
        Ah[i] = pack2(hi.x, hi.x);  Bh[i] = pack2(-hi.y, hi.y);
        Al[i] = pack2(lo.x, lo.x);  Bl[i] = pack2(-lo.y, lo.y);
    }
#pragma unroll
    for (int r = 0; r < NR; r++) {
        u64 a = st[r].x, b = st[r].y;
        a = ffma2(Bh[r >> 2], swap2(a), fmul2(Ah[r >> 2], a));
        b = ffma2(Bh[r >> 2], swap2(b), fmul2(Ah[r >> 2], b));
        a = ffma2(Bl[r & 3],  swap2(a), fmul2(Al[r & 3],  a));
        b = ffma2(Bl[r & 3],  swap2(b), fmul2(Al[r & 3],  b));
        st[r].x = a; st[r].y = b;
    }
}
__device__ __forceinline__ void diag_D(ulonglong2* st, int t, const float2 (*P)[2]) {
    float2 p01 = cmul(P[4][(t >> 7) & 1], P[5][(t >> 6) & 1]);
    float2 p23 = cmul(P[6][(t >> 5) & 1], P[7][(t >> 4) & 1]);
    float2 p45 = cmul(P[8][(t >> 3) & 1], P[9][(t >> 2) & 1]);
    float2 p67 = cmul(P[10][(t >> 1) & 1], P[11][t & 1]);
    float2 ph  = cmul(cmul(p01, p23), cmul(p45, p67));
    u64 Ah[4], Bh[4], Al[4], Bl[4];
#pragma unroll
    for (int i = 0; i < 4; i++) {
        float2 hi = cmul(ph, cmul(P[0][(i >> 1) & 1], P[1][i & 1]));
        float2 lo = cmul(P[2][(i >> 1) & 1], P[3][i & 1]);
        Ah[i] = pack2(hi.x, hi.x);  Bh[i] = pack2(-hi.y, hi.y);
        Al[i] = pack2(lo.x, lo.x);  Bl[i] = pack2(-lo.y, lo.y);
    }
#pragma unroll
    for (int r = 0; r < NR; r++) {
        u64 a = st[r].x, b = st[r].y;
        a = ffma2(Bh[r >> 2], swap2(a), fmul2(Ah[r >> 2], a));
        b = ffma2(Bh[r >> 2], swap2(b), fmul2(Ah[r >> 2], b));
        a = ffma2(Bl[r & 3],  swap2(a), fmul2(Al[r & 3],  a));
        b = ffma2(Bl[r & 3],  swap2(b), fmul2(Al[r & 3],  b));
        st[r].x = a; st[r].y = b;
    }
}

// ======================= batched CNOT ring (shared indices, 128-bit data) =======================
template<bool LAYOUT_A>
__device__ __forceinline__ void cnotx(ulonglong2* st, int t, ulonglong2* x, const unsigned* U) {
    uint4 ua = *(const uint4*)(U + (LAYOUT_A ? 4 : 0));
    uint4 ub = *(const uint4*)(U + (LAYOUT_A ? 8 : 4));
    unsigned v0 = 0;
    if (t & 1)   v0 ^= ua.x;
    if (t & 2)   v0 ^= ua.y;
    if (t & 4)   v0 ^= ua.z;
    if (t & 8)   v0 ^= ua.w;
    if (t & 16)  v0 ^= ub.x;
    if (t & 32)  v0 ^= ub.y;
    if (t & 64)  v0 ^= ub.z;
    if (t & 128) v0 ^= ub.w;
#pragma unroll
    for (int r = 0; r < NR; r++) {
        unsigned n = LAYOUT_A ? (((unsigned)t << 4) | (unsigned)r)
                              : (((unsigned)r << 8) | (unsigned)t);
        x[PHYS(n)] = st[r];
    }
    __syncthreads();
    uint4 ur = *(const uint4*)(U + (LAYOUT_A ? 0 : 8));
#pragma unroll
    for (int r = 0; r < NR; r++) {            // r compile-time -> constant-folded XORs
        unsigned m = v0;
        if (r & 8) m ^= ur.w;
        if (r & 4) m ^= ur.z;
        if (r & 2) m ^= ur.y;
        if (r & 1) m ^= ur.x;
        st[r] = x[PHYS(m)];
    }
}

// GF(2) ring transform (reverse order), setup threads only.
__device__ __forceinline__ unsigned ring_map(unsigned v, unsigned mask) {
#pragma unroll
    for (int k = NQ - 1; k >= 0; k--) {
        if (mask & (1u << k)) {
            const int cb = 11 - k;
            const int tb = 11 - ((k + 1) % NQ);
            v ^= ((v >> cb) & 1u) << tb;
        }
    }
    return v;
}

// packed-pair warp reduction: lo and hi lanes reduced independently
__device__ __forceinline__ u64 wred2(u64 v) {
#pragma unroll
    for (int o = 16; o; o >>= 1) v = add2(v, __shfl_xor_sync(0xFFFFFFFFu, v, o));
    return v;
}

__global__ void __launch_bounds__(NT)
qsim_kernel(const float* __restrict__ x,       // (B, 12)
            const float* __restrict__ w,       // (4, 12, 3)
            const float* __restrict__ ent,     // (4, 12)
            float* __restrict__ out)           // (B, 12)
{
    extern __shared__ __align__(16) ulonglong2 dsm[];   // 2 exchange buffers
    ulonglong2* x0 = dsm;                                // sweep exchanges + WL
    ulonglong2* x1 = dsm + XSZ;                          // cnot permutations

    __shared__ __align__(16) u64 Usm[48 * 4];            // RY coeffs (shared)
    __shared__ float2 Phs1[48][2];                       // RZ(phi) phases
    __shared__ float2 Phs2[48][2];                       // RZ(omega) phases
    __shared__ u64 red[(NT / 32) * NQ];                  // packed pair reductions
    __shared__ float2 encV[2][NQ][2];                    // per-sample encoding amps
    __shared__ unsigned maskbits[NLAYERS];
    __shared__ __align__(16) unsigned units_sm[NLAYERS][16];

    const int b0   = blockIdx.x * 2;
    const int t    = threadIdx.x;
    const int lane = t & 31;
    const int wid  = t >> 5;

    // ---- precompute (weights shared, encoding per sample) ----
    if (t < 128) {
        const float PI = 3.14159265358979323846f;
        if (t < 2 * NQ) {
            int s = t / NQ, q = t % NQ;
            float xv = __ldg(&x[(b0 + s) * NQ + q]);
            float sn, c;  sincosf(0.5f * PI * xv, &sn, &c);
            float sh, ch; sincosf(0.5f * PI * xv * xv, &sh, &ch);
            float2 a0 = make_float2( c * ch, -c * sh);
            float2 a1 = make_float2( sn * ch,  sn * sh);
            float pf = __ldg(&w[q * 3 + 0]);          // layer 0 phi
            float sp, cp; sincosf(0.5f * pf, &sp, &cp);
            encV[s][q][0] = cmul(a0, make_float2(cp, -sp));
            encV[s][q][1] = cmul(a1, make_float2(cp,  sp));
        } else if (t < 24 + 48) {
            int gi = t - 24;   // 0..47
            float phi = __ldg(&w[gi * 3 + 0]);
            float th  = __ldg(&w[gi * 3 + 1]);
            float om  = __ldg(&w[gi * 3 + 2]);
            float sn, c;  sincosf(0.5f * th, &sn, &c);
            u64* g = &Usm[gi * 4];
            g[0] = pack2(c, c);  g[1] = pack2(sn, sn);  g[2] = pack2(-sn, -sn);
            float sp, cp; sincosf(0.5f * phi, &sp, &cp);
            Phs1[gi][0] = make_float2(cp, -sp);
            Phs1[gi][1] = make_float2(cp,  sp);
            float so, co; sincosf(0.5f * om, &so, &co);
            Phs2[gi][0] = make_float2(co, -so);
            Phs2[gi][1] = make_float2(co,  so);
        } else if (t < 76) {
            int l = t - 72;
            unsigned mm = 0;
#pragma unroll
            for (int i = 0; i < NQ; i++)
                mm |= (__ldg(&ent[l * NQ + i]) > 0.5f ? 1u : 0u) << i;
            maskbits[l] = mm;
        }
    }
    __syncthreads();

    // ---- ring-perm unit images (threads 128..175); consumed after next CTA bar ----
    if (t >= 128 && t < 128 + NLAYERS * NQ) {
        int idx = t - 128, l = idx / NQ, i = idx % NQ;
        units_sm[l][i] = ring_map(1u << i, maskbits[l]);
    }

    // ---- product-state init for both samples, layout D, interleaved ----
    ulonglong2 st[NR];
#pragma unroll
    for (int s = 0; s < 2; s++) {
        const float2 (*eV)[2] = encV[s];
        float2 q45 = cmul(eV[4][(t >> 7) & 1], eV[5][(t >> 6) & 1]);
        float2 q67 = cmul(eV[6][(t >> 5) & 1], eV[7][(t >> 4) & 1]);
        float2 q89 = cmul(eV[8][(t >> 3) & 1], eV[9][(t >> 2) & 1]);
        float2 qAB = cmul(eV[10][(t >> 1) & 1], eV[11][t & 1]);
        float2 cm  = cmul(cmul(q45, q67), cmul(q89, qAB));
        float2 p01[4], p23[4];
#pragma unroll
        for (int i = 0; i < 4; i++) {
            p01[i] = cmul(eV[0][(i >> 1) & 1], eV[1][i & 1]);
            p23[i] = cmul(eV[2][(i >> 1) & 1], eV[3][i & 1]);
        }
#pragma unroll
        for (int r = 0; r < NR; r++) {
            float2 a = cmul(cmul(p01[r >> 2], p23[r & 3]), cm);
            if (s == 0) st[r].x = pack2(a.x, a.y);
            else        st[r].y = pack2(a.x, a.y);
        }
    }

    // ---- layers (R13 schedule; both samples ride every op) ----
    {
        sweep_D_to_A(st, Usm +  0 * 48, t, x0);
        diag_A(st, t, &Phs2[0]);
        cnotx<true>(st, t, x1, units_sm[0]);
        diag_A(st, t, &Phs1[12]);

        sweep_A_to_D(st, Usm +  1 * 48, t, x0);
        diag_D(st, t, &Phs2[12]);
        cnotx<false>(st, t, x1, units_sm[1]);
        diag_D(st, t, &Phs1[24]);

        sweep_D_to_A(st, Usm +  2 * 48, t, x0);
        diag_A(st, t, &Phs2[24]);
        cnotx<true>(st, t, x1, units_sm[2]);
        diag_A(st, t, &Phs1[36]);

        sweep_A_to_D(st, Usm +  3 * 48, t, x0);
        // D2_3 dropped: |amp|^2 is phase-invariant
        cnotx<false>(st, t, x1, units_sm[3]);
    }

    // ---- readout, layout D, both samples packed (lo=a, hi=b) ----
    float psA = 0.f, a0A = 0.f, a1A = 0.f, a2A = 0.f, a3A = 0.f;
    float psB = 0.f, a0B = 0.f, a1B = 0.f, a2B = 0.f, a3B = 0.f;
#pragma unroll
    for (int r = 0; r < NR; r++) {
        float re, im;
        unpack2(st[r].x, re, im);
        float pa = fmaf(re, re, im * im);
        unpack2(st[r].y, re, im);
        float pb = fmaf(re, re, im * im);
        psA += pa;                      psB += pb;
        a0A += (r & 8) ? -pa : pa;      a0B += (r & 8) ? -pb : pb;
        a1A += (r & 4) ? -pa : pa;      a1B += (r & 4) ? -pb : pb;
        a2A += (r & 2) ? -pa : pa;      a2B += (r & 2) ? -pb : pb;
        a3A += (r & 1) ? -pa : pa;      a3B += (r & 1) ? -pb : pb;
    }
    u64 ps  = pack2(psA, psB);
    u64 r0  = wred2(pack2(a0A, a0B));
    u64 r1  = wred2(pack2(a1A, a1B));
    u64 r2  = wred2(pack2(a2A, a2B));
    u64 r3  = wred2(pack2(a3A, a3B));
    u64 pss = wred2(ps);
    u64 s7  = wred2((lane & 16) ? neg2(ps) : ps);
    u64 s8  = wred2((lane &  8) ? neg2(ps) : ps);
    u64 s9  = wred2((lane &  4) ? neg2(ps) : ps);
    u64 s10 = wred2((lane &  2) ? neg2(ps) : ps);
    u64 s11 = wred2((lane &  1) ? neg2(ps) : ps);
    if (lane == 0) {
        u64* rw = &red[wid * NQ];
        rw[0] = r0;  rw[1] = r1;  rw[2] = r2;  rw[3] = r3;
        rw[4] = (wid & 4) ? neg2(pss) : pss;
        rw[5] = (wid & 2) ? neg2(pss) : pss;
        rw[6] = (wid & 1) ? neg2(pss) : pss;
        rw[7] = s7;  rw[8] = s8;  rw[9] = s9;  rw[10] = s10;  rw[11] = s11;
    }
    __syncthreads();

    if (t < NQ) {
        u64 s = red[t];
#pragma unroll
        for (int wi = 1; wi < NT / 32; wi++) s = add2(s, red[wi * NQ + t]);
        float va, vb; unpack2(s, va, vb);
        out[b0 * NQ + t]       = va;   // SCALE = 1
        out[(b0 + 1) * NQ + t] = vb;
    }
}

extern "C" void kernel_launch(void* const* d_in, const int* in_sizes, int n_in,
                              void* d_out, int out_size)
{
    const float* x   = (const float*)d_in[0];   // (B, 12)
    const float* w   = (const float*)d_in[1];   // (4, 12, 3)
    const float* ent = (const float*)d_in[2];   // (4, 12)
    float* out = (float*)d_out;                 // (B, 12)

    const size_t shmem = 2 * XSZ * sizeof(ulonglong2);  // 139264 B dynamic
    cudaFuncSetAttribute((const void*)qsim_kernel,
                         cudaFuncAttributeMaxDynamicSharedMemorySize, (int)shmem);

    int B = in_sizes[0] / NQ;
    qsim_kernel<<<B / 2, NT, shmem>>>(x, w, ent, out);
}